// round 7
// baseline (speedup 1.0000x reference)
#include <cuda_runtime.h>
#include <cuda_bf16.h>
#include <cstdint>

// BinaryBiaffine2 via warp-level bf16 mma.sync: scores = leaky(X@W+b)@Wc, broadcast add.
// fp32 -> 2-way bf16 split (hi+lo), 3 cross-term GEMMs fused as K-steps.
// R7: 3-stage cp.async pipeline, single __syncthreads per k-chunk,
//     FIXED wait-group ledger (no empty commits; WAIT0 on final iter).

#define D_DIM 1024
#define M_DIM 500
#define NC    1000
#define NPAD  1024
#define BL_MAX 16384
#define NEG   0.01f

#define MT 128
#define NT 128
#define NCHUNK 32
#define GTHREADS 256

// dynamic smem: 3 stages x (A 16KB + B 16KB) + tables
#define SM_STAGE 32768
#define SM_TAB   (3 * SM_STAGE)
#define SM_TOTAL (SM_TAB + 2048)

// ---- scratch (static device globals; allocation-guard-safe) ----
__device__ __nv_bfloat16 g_Xi[(size_t)BL_MAX * 2048];   // [row][chunk*64 + half*32 + j]
__device__ __nv_bfloat16 g_Bi[(size_t)NPAD * 2048];     // [n][chunk*64 + half*32 + j]
__device__ float g_partD[8][BL_MAX][2];                 // per-column-tile dep partials
__device__ float g_partH[8][BL_MAX][2];                 // per-column-tile head partials
__device__ float g_scores[BL_MAX * 4];                  // final: dep [0,2BL), head [2BL,4BL)

// ============================ PTX helpers ============================
__device__ __forceinline__ uint32_t smem_u32(const void* p) {
    uint32_t a;
    asm("{ .reg .u64 t; cvta.to.shared.u64 t, %1; cvt.u32.u64 %0, t; }" : "=r"(a) : "l"(p));
    return a;
}
#define SWZ128(x) ((x) ^ (((x) >> 3) & 0x70))

#define CP_ASYNC16(dst, src) \
    asm volatile("cp.async.cg.shared.global [%0], [%1], 16;" :: "r"(dst), "l"(src))
#define CP_COMMIT() asm volatile("cp.async.commit_group;" ::: "memory")
#define CP_WAIT1()  asm volatile("cp.async.wait_group 1;" ::: "memory")
#define CP_WAIT0()  asm volatile("cp.async.wait_group 0;" ::: "memory")

#define LDSM_X4(r0, r1, r2, r3, addr) \
    asm volatile("ldmatrix.sync.aligned.m8n8.x4.shared.b16 {%0,%1,%2,%3}, [%4];" \
                 : "=r"(r0), "=r"(r1), "=r"(r2), "=r"(r3) : "r"(addr))

#define MMA16816(d, a0, a1, a2, a3, b0, b1) \
    asm volatile("mma.sync.aligned.m16n8k16.row.col.f32.bf16.bf16.f32 " \
                 "{%0,%1,%2,%3}, {%4,%5,%6,%7}, {%8,%9}, {%0,%1,%2,%3};" \
                 : "+f"((d)[0]), "+f"((d)[1]), "+f"((d)[2]), "+f"((d)[3]) \
                 : "r"(a0), "r"(a1), "r"(a2), "r"(a3), "r"(b0), "r"(b1))

// ============================ converters ============================
__global__ void convX(const float* __restrict__ X) {
    size_t i = (size_t)blockIdx.x * blockDim.x + threadIdx.x;   // one float4 each
    const float4 v = reinterpret_cast<const float4*>(X)[i];
    size_t row = i >> 8;              // 256 float4 per 1024-col row
    int col = (int)(i & 255) * 4;
    int chunk = col >> 5, j = col & 31;
    __nv_bfloat16* o = g_Xi + row * 2048 + (size_t)chunk * 64 + j;

    __nv_bfloat16 h0 = __float2bfloat16(v.x), h1 = __float2bfloat16(v.y);
    __nv_bfloat16 h2 = __float2bfloat16(v.z), h3 = __float2bfloat16(v.w);
    __nv_bfloat16 l0 = __float2bfloat16(v.x - __bfloat162float(h0));
    __nv_bfloat16 l1 = __float2bfloat16(v.y - __bfloat162float(h1));
    __nv_bfloat16 l2 = __float2bfloat16(v.z - __bfloat162float(h2));
    __nv_bfloat16 l3 = __float2bfloat16(v.w - __bfloat162float(h3));

    __nv_bfloat162* oh = reinterpret_cast<__nv_bfloat162*>(o);
    __nv_bfloat162* ol = reinterpret_cast<__nv_bfloat162*>(o + 32);
    oh[0] = __nv_bfloat162(h0, h1); oh[1] = __nv_bfloat162(h2, h3);
    ol[0] = __nv_bfloat162(l0, l1); ol[1] = __nv_bfloat162(l2, l3);
}

// Transpose W_dep|W_head (fp32 [d][m]) into g_Bi [n][2048] bf16 hi|lo interleaved.
__global__ void convW(const float* __restrict__ Wd, const float* __restrict__ Wh, int y0) {
    __shared__ float t[32][33];
    const int m0 = blockIdx.x * 32, d0 = (blockIdx.y + y0) * 32;
    const int tx = threadIdx.x, ty = threadIdx.y;     // 32 x 8
    #pragma unroll
    for (int yy = ty; yy < 32; yy += 8) {
        int m = m0 + tx, d = d0 + yy;
        float v = 0.0f;
        if (m < M_DIM)      v = Wd[(size_t)d * M_DIM + m];
        else if (m < NC)    v = Wh[(size_t)d * M_DIM + (m - M_DIM)];
        t[yy][tx] = v;
    }
    __syncthreads();
    #pragma unroll
    for (int yy = ty; yy < 32; yy += 8) {
        int n = m0 + yy;
        float v = t[tx][yy];
        __nv_bfloat16 h = __float2bfloat16(v);
        __nv_bfloat16 l = __float2bfloat16(v - __bfloat162float(h));
        size_t ob = (size_t)n * 2048 + (size_t)(d0 >> 5) * 64 + tx;
        g_Bi[ob] = h;
        g_Bi[ob + 32] = l;
    }
}

// ============================ HMMA GEMM + fused epilogue ============================
__global__ __launch_bounds__(GTHREADS, 2)
void gemm_mma(const float* __restrict__ bd, const float* __restrict__ bh,
              const float* __restrict__ Wc)
{
    extern __shared__ char dsm[];
    const uint32_t sbase = smem_u32(dsm);

    const int tid = threadIdx.x;
    const int wid = tid >> 5, lid = tid & 31;
    const int CB  = blockIdx.x * NT;      // n base
    const int R   = blockIdx.y * MT;      // m base

    float* sbias = reinterpret_cast<float*>(dsm + SM_TAB);
    float* sw0   = sbias + 128;
    float* sw1   = sbias + 256;
    int*   sdep  = reinterpret_cast<int*>(sbias + 384);

    if (tid < 128) {
        int n = CB + tid;
        float bias = 0.f, w0 = 0.f, w1 = 0.f; int dep = 0;
        if (n < M_DIM)      { bias = bd[n]; w0 = Wc[2*n]; w1 = Wc[2*n+1]; dep = 1; }
        else if (n < NC)    { bias = bh[n - M_DIM]; w0 = Wc[2*n]; w1 = Wc[2*n+1]; }
        sbias[tid] = bias; sw0[tid] = w0; sw1[tid] = w1; sdep[tid] = dep;
    }

    const __nv_bfloat16* Ag = g_Xi + (size_t)R * 2048;
    const __nv_bfloat16* Bg = g_Bi + (size_t)CB * 2048;

    // ldmatrix lane address components
    const int laneA_r = (lid & 7) | (((lid >> 3) & 1) << 3);   // row within 16
    const int laneA_k = (lid >> 4) << 3;                       // 0 or 8
    const int laneB_n = (lid & 7) | ((lid >> 4) << 3);         // n within 16
    const int laneB_k = ((lid >> 3) & 1) << 3;                 // 0 or 8

    const int wm = wid & 3;           // m group: rows wm*32 .. +31
    const int wn = wid >> 2;          // n group: cols wn*64 .. +63
    const int mBase = wm * 32;
    const int nBase = wn * 64;

    float acc[2][8][4];
    #pragma unroll
    for (int i = 0; i < 2; ++i)
        #pragma unroll
        for (int j = 0; j < 8; ++j)
            #pragma unroll
            for (int e = 0; e < 4; ++e) acc[i][j][e] = 0.f;

    // cp.async mapping (per thread)
    const int ld_r   = tid >> 3;                 // base row (0..31), +32 per i
    const int ld_c16 = (tid & 7) * 16;           // byte col
    const uint32_t ld_dofs[4] = {
        SWZ128((ld_r +  0) * 128 + ld_c16),
        SWZ128((ld_r + 32) * 128 + ld_c16),
        SWZ128((ld_r + 64) * 128 + ld_c16),
        SWZ128((ld_r + 96) * 128 + ld_c16)
    };

    // prologue: issue chunks 0 and 1 into stages 0, 1 (one commit group each)
    #pragma unroll
    for (int pc = 0; pc < 2; ++pc) {
        const char* An = (const char*)(Ag + pc * 64);
        const char* Bn = (const char*)(Bg + pc * 64);
        const uint32_t st = sbase + pc * SM_STAGE;
        #pragma unroll
        for (int i = 0; i < 4; ++i) {
            size_t ro = (size_t)(ld_r + i * 32) * 4096 + ld_c16;
            CP_ASYNC16(st + ld_dofs[i],         An + ro);
            CP_ASYNC16(st + 16384 + ld_dofs[i], Bn + ro);
        }
        CP_COMMIT();
    }

    // cross-term k-step tables: (A kcol, B kcol) in bf16 units
    const int AKC[6] = {0, 16, 0, 16, 32, 48};
    const int BKC[6] = {0, 16, 32, 48, 0, 16};

    int s_cur = 0, s_nxt = 2;                    // stage indices mod 3
    for (int it = 0; it < NCHUNK; ++it) {
        // wait-group ledger (real groups only):
        //   it <= NCHUNK-2: pending {it, it+1} -> WAIT1 guarantees chunk it landed
        //   it == NCHUNK-1: pending {it}       -> WAIT0 guarantees it landed
        if (it < NCHUNK - 1) { CP_WAIT1(); } else { CP_WAIT0(); }
        __syncthreads();            // data visible; all warps done computing stage s_nxt

        if (it + 2 < NCHUNK) {      // prefetch chunk it+2 into stage s_nxt
            const char* An = (const char*)(Ag + (it + 2) * 64);
            const char* Bn = (const char*)(Bg + (it + 2) * 64);
            const uint32_t st = sbase + s_nxt * SM_STAGE;
            #pragma unroll
            for (int i = 0; i < 4; ++i) {
                size_t ro = (size_t)(ld_r + i * 32) * 4096 + ld_c16;
                CP_ASYNC16(st + ld_dofs[i],         An + ro);
                CP_ASYNC16(st + 16384 + ld_dofs[i], Bn + ro);
            }
            CP_COMMIT();            // commit ONLY real groups (ledger above depends on it)
        }

        const uint32_t pA = sbase + s_cur * SM_STAGE;
        const uint32_t pB = pA + 16384;

        #pragma unroll
        for (int s = 0; s < 6; ++s) {
            const int akc = AKC[s], bkc = BKC[s];
            uint32_t a[2][4];
            #pragma unroll
            for (int mi = 0; mi < 2; ++mi) {
                uint32_t addr = pA + SWZ128((mBase + mi * 16 + laneA_r) * 128 +
                                            (akc + laneA_k) * 2);
                LDSM_X4(a[mi][0], a[mi][1], a[mi][2], a[mi][3], addr);
            }
            #pragma unroll
            for (int nfp = 0; nfp < 4; ++nfp) {
                uint32_t b0, b1, b2, b3;
                uint32_t addr = pB + SWZ128((nBase + nfp * 16 + laneB_n) * 128 +
                                            (bkc + laneB_k) * 2);
                LDSM_X4(b0, b1, b2, b3, addr);
                MMA16816(acc[0][2 * nfp],     a[0][0], a[0][1], a[0][2], a[0][3], b0, b1);
                MMA16816(acc[1][2 * nfp],     a[1][0], a[1][1], a[1][2], a[1][3], b0, b1);
                MMA16816(acc[0][2 * nfp + 1], a[0][0], a[0][1], a[0][2], a[0][3], b2, b3);
                MMA16816(acc[1][2 * nfp + 1], a[1][0], a[1][1], a[1][2], a[1][3], b2, b3);
            }
        }

        s_cur = (s_cur + 1) == 3 ? 0 : s_cur + 1;
        s_nxt = (s_nxt + 1) == 3 ? 0 : s_nxt + 1;
    }

    // ---- epilogue: bias + leaky + Wc reduce -> per-tile partial scores ----
    float pd0[4], pd1[4], ph0[4], ph1[4];
    #pragma unroll
    for (int i = 0; i < 4; ++i) { pd0[i] = pd1[i] = ph0[i] = ph1[i] = 0.f; }

    #pragma unroll
    for (int mi = 0; mi < 2; ++mi)
        #pragma unroll
        for (int nf = 0; nf < 8; ++nf)
            #pragma unroll
            for (int e = 0; e < 4; ++e) {
                int nl = nBase + nf * 8 + (lid & 3) * 2 + (e & 1);
                float v = acc[mi][nf][e] + sbias[nl];
                v = v > 0.f ? v : NEG * v;
                float w0 = sw0[nl], w1 = sw1[nl];
                int ri = mi * 2 + (e >> 1);
                if (sdep[nl]) { pd0[ri] += v * w0; pd1[ri] += v * w1; }
                else          { ph0[ri] += v * w0; ph1[ri] += v * w1; }
            }

    #pragma unroll
    for (int off = 2; off >= 1; off >>= 1)
        #pragma unroll
        for (int i = 0; i < 4; ++i) {
            pd0[i] += __shfl_xor_sync(0xffffffffu, pd0[i], off);
            pd1[i] += __shfl_xor_sync(0xffffffffu, pd1[i], off);
            ph0[i] += __shfl_xor_sync(0xffffffffu, ph0[i], off);
            ph1[i] += __shfl_xor_sync(0xffffffffu, ph1[i], off);
        }

    // combine wn=0 and wn=1 halves via smem stage (reuse stage 0 buffer)
    float* stage = reinterpret_cast<float*>(dsm);
    __syncthreads();   // all compute reads done -> safe to reuse smem

    if ((lid & 3) == 0 && wn == 0) {
        #pragma unroll
        for (int i = 0; i < 4; ++i) {
            int rl = mBase + (i >> 1) * 16 + (lid >> 2) + (i & 1) * 8;
            stage[rl * 4 + 0] = pd0[i];
            stage[rl * 4 + 1] = pd1[i];
            stage[rl * 4 + 2] = ph0[i];
            stage[rl * 4 + 3] = ph1[i];
        }
    }
    __syncthreads();
    if ((lid & 3) == 0 && wn == 1) {
        const int tile = blockIdx.x;
        #pragma unroll
        for (int i = 0; i < 4; ++i) {
            int rl = mBase + (i >> 1) * 16 + (lid >> 2) + (i & 1) * 8;
            int row = R + rl;
            g_partD[tile][row][0] = pd0[i] + stage[rl * 4 + 0];
            g_partD[tile][row][1] = pd1[i] + stage[rl * 4 + 1];
            g_partH[tile][row][0] = ph0[i] + stage[rl * 4 + 2];
            g_partH[tile][row][1] = ph1[i] + stage[rl * 4 + 3];
        }
    }
}

// sum the 8 column-tile partials -> g_scores
__global__ __launch_bounds__(256)
void reduce_scores()
{
    int row = blockIdx.x * blockDim.x + threadIdx.x;
    float d0 = 0.f, d1 = 0.f, h0 = 0.f, h1 = 0.f;
    #pragma unroll
    for (int t = 0; t < 8; ++t) {
        d0 += g_partD[t][row][0];
        d1 += g_partD[t][row][1];
        h0 += g_partH[t][row][0];
        h1 += g_partH[t][row][1];
    }
    g_scores[row * 2 + 0] = d0;
    g_scores[row * 2 + 1] = d1;
    g_scores[2 * BL_MAX + row * 2 + 0] = h0;
    g_scores[2 * BL_MAX + row * 2 + 1] = h1;
}

// out[b, i, j, c] = dep[b,i,c] + head[b,j,c] + bc[c]
__global__ __launch_bounds__(256)
void bcast_kernel(const float* __restrict__ bc, float* __restrict__ out)
{
    const float* ds = g_scores;
    const float* hs = g_scores + 2 * BL_MAX;
    const int n = blockIdx.x;                  // b*1024 + i
    const int b = n >> 10;
    const float base0 = ds[n * 2 + 0] + bc[0];
    const float base1 = ds[n * 2 + 1] + bc[1];
    const float4* hv = reinterpret_cast<const float4*>(hs + (size_t)b * 2048);
    float4* o = reinterpret_cast<float4*>(out + (size_t)n * 2048);
    #pragma unroll
    for (int t = threadIdx.x; t < 512; t += 256) {
        float4 h = hv[t];
        o[t] = make_float4(base0 + h.x, base1 + h.y, base0 + h.z, base1 + h.w);
    }
}

extern "C" void kernel_launch(void* const* d_in, const int* in_sizes, int n_in,
                              void* d_out, int out_size)
{
    const float* X  = (const float*)d_in[0];
    const float* Wd = (const float*)d_in[1];
    const float* bd = (const float*)d_in[2];
    const float* Wh = (const float*)d_in[3];
    const float* bh = (const float*)d_in[4];
    const float* Wc = (const float*)d_in[5];
    const float* bc = (const float*)d_in[6];
    float* out = (float*)d_out;

    const int BL = in_sizes[0] / D_DIM;        // 16384

    static int smem_set = 0;
    if (!smem_set) {
        cudaFuncSetAttribute(gemm_mma, cudaFuncAttributeMaxDynamicSharedMemorySize, SM_TOTAL);
        smem_set = 1;
    }

    // harness issues ~2 internal launches first; ncu -s 5 -c 1 captures MY index 3 = gemm_mma
    convW<<<dim3(32, 16), dim3(32, 8)>>>(Wd, Wh, 0);                 // 0
    convW<<<dim3(32, 16), dim3(32, 8)>>>(Wd, Wh, 16);                // 1
    convX<<<(BL * D_DIM / 4 + 255) / 256, 256>>>(X);                 // 2
    gemm_mma<<<dim3(NPAD / NT, BL / MT), GTHREADS, SM_TOTAL>>>(bd, bh, Wc);  // 3
    reduce_scores<<<BL / 256, 256>>>();                              // 4
    bcast_kernel<<<BL, 256>>>(bc, out);                              // 5
}

// round 9
// speedup vs baseline: 1.1442x; 1.1442x over previous
#include <cuda_runtime.h>
#include <cuda_bf16.h>
#include <cstdint>

// BinaryBiaffine2 via warp-level bf16 mma.sync: scores = leaky(X@W+b)@Wc, broadcast add.
// fp32 -> 2-way bf16 split (hi+lo), 3 cross-term GEMMs fused as K-steps.
// R8/R9: mainloop = R5 skeleton (2-stage, prefetch-before-wait, 2 barriers — measured best);
//        inner compute: all 6 LDSM.x4 per k-step issued before the 16 MMAs.

#define D_DIM 1024
#define M_DIM 500
#define NC    1000
#define NPAD  1024
#define BL_MAX 16384
#define NEG   0.01f

#define MT 128
#define NT 128
#define NCHUNK 32
#define GTHREADS 256

// dynamic smem layout (2-stage)
#define SM_A0 0
#define SM_A1 16384
#define SM_B0 32768
#define SM_B1 49152
#define SM_TAB 65536
#define SM_TOTAL (65536 + 2048)

// ---- scratch (static device globals; allocation-guard-safe) ----
__device__ __nv_bfloat16 g_Xi[(size_t)BL_MAX * 2048];   // [row][chunk*64 + half*32 + j]
__device__ __nv_bfloat16 g_Bi[(size_t)NPAD * 2048];     // [n][chunk*64 + half*32 + j]
__device__ float g_partD[8][BL_MAX][2];                 // per-column-tile dep partials
__device__ float g_partH[8][BL_MAX][2];                 // per-column-tile head partials
__device__ float g_scores[BL_MAX * 4];                  // final: dep [0,2BL), head [2BL,4BL)

// ============================ PTX helpers ============================
__device__ __forceinline__ uint32_t smem_u32(const void* p) {
    uint32_t a;
    asm("{ .reg .u64 t; cvta.to.shared.u64 t, %1; cvt.u32.u64 %0, t; }" : "=r"(a) : "l"(p));
    return a;
}
#define SWZ128(x) ((x) ^ (((x) >> 3) & 0x70))

#define CP_ASYNC16(dst, src) \
    asm volatile("cp.async.cg.shared.global [%0], [%1], 16;" :: "r"(dst), "l"(src))
#define CP_COMMIT() asm volatile("cp.async.commit_group;" ::: "memory")
#define CP_WAIT1()  asm volatile("cp.async.wait_group 1;" ::: "memory")
#define CP_WAIT0()  asm volatile("cp.async.wait_group 0;" ::: "memory")

#define LDSM_X4(r0, r1, r2, r3, addr) \
    asm volatile("ldmatrix.sync.aligned.m8n8.x4.shared.b16 {%0,%1,%2,%3}, [%4];" \
                 : "=r"(r0), "=r"(r1), "=r"(r2), "=r"(r3) : "r"(addr))

#define MMA16816(d, a0, a1, a2, a3, b0, b1) \
    asm volatile("mma.sync.aligned.m16n8k16.row.col.f32.bf16.bf16.f32 " \
                 "{%0,%1,%2,%3}, {%4,%5,%6,%7}, {%8,%9}, {%0,%1,%2,%3};" \
                 : "+f"((d)[0]), "+f"((d)[1]), "+f"((d)[2]), "+f"((d)[3]) \
                 : "r"(a0), "r"(a1), "r"(a2), "r"(a3), "r"(b0), "r"(b1))

// ============================ converters ============================
__global__ void convX(const float* __restrict__ X) {
    size_t i = (size_t)blockIdx.x * blockDim.x + threadIdx.x;   // one float4 each
    const float4 v = reinterpret_cast<const float4*>(X)[i];
    size_t row = i >> 8;              // 256 float4 per 1024-col row
    int col = (int)(i & 255) * 4;
    int chunk = col >> 5, j = col & 31;
    __nv_bfloat16* o = g_Xi + row * 2048 + (size_t)chunk * 64 + j;

    __nv_bfloat16 h0 = __float2bfloat16(v.x), h1 = __float2bfloat16(v.y);
    __nv_bfloat16 h2 = __float2bfloat16(v.z), h3 = __float2bfloat16(v.w);
    __nv_bfloat16 l0 = __float2bfloat16(v.x - __bfloat162float(h0));
    __nv_bfloat16 l1 = __float2bfloat16(v.y - __bfloat162float(h1));
    __nv_bfloat16 l2 = __float2bfloat16(v.z - __bfloat162float(h2));
    __nv_bfloat16 l3 = __float2bfloat16(v.w - __bfloat162float(h3));

    __nv_bfloat162* oh = reinterpret_cast<__nv_bfloat162*>(o);
    __nv_bfloat162* ol = reinterpret_cast<__nv_bfloat162*>(o + 32);
    oh[0] = __nv_bfloat162(h0, h1); oh[1] = __nv_bfloat162(h2, h3);
    ol[0] = __nv_bfloat162(l0, l1); ol[1] = __nv_bfloat162(l2, l3);
}

// Transpose W_dep|W_head (fp32 [d][m]) into g_Bi [n][2048] bf16 hi|lo interleaved.
__global__ void convW(const float* __restrict__ Wd, const float* __restrict__ Wh, int y0) {
    __shared__ float t[32][33];
    const int m0 = blockIdx.x * 32, d0 = (blockIdx.y + y0) * 32;
    const int tx = threadIdx.x, ty = threadIdx.y;     // 32 x 8
    #pragma unroll
    for (int yy = ty; yy < 32; yy += 8) {
        int m = m0 + tx, d = d0 + yy;
        float v = 0.0f;
        if (m < M_DIM)      v = Wd[(size_t)d * M_DIM + m];
        else if (m < NC)    v = Wh[(size_t)d * M_DIM + (m - M_DIM)];
        t[yy][tx] = v;
    }
    __syncthreads();
    #pragma unroll
    for (int yy = ty; yy < 32; yy += 8) {
        int n = m0 + yy;
        float v = t[tx][yy];
        __nv_bfloat16 h = __float2bfloat16(v);
        __nv_bfloat16 l = __float2bfloat16(v - __bfloat162float(h));
        size_t ob = (size_t)n * 2048 + (size_t)(d0 >> 5) * 64 + tx;
        g_Bi[ob] = h;
        g_Bi[ob + 32] = l;
    }
}

// ============================ HMMA GEMM + fused epilogue ============================
__global__ __launch_bounds__(GTHREADS, 2)
void gemm_mma(const float* __restrict__ bd, const float* __restrict__ bh,
              const float* __restrict__ Wc)
{
    extern __shared__ char dsm[];
    const uint32_t sbase = smem_u32(dsm);

    const int tid = threadIdx.x;
    const int wid = tid >> 5, lid = tid & 31;
    const int CB  = blockIdx.x * NT;      // n base
    const int R   = blockIdx.y * MT;      // m base

    float* sbias = reinterpret_cast<float*>(dsm + SM_TAB);
    float* sw0   = sbias + 128;
    float* sw1   = sbias + 256;
    int*   sdep  = reinterpret_cast<int*>(sbias + 384);

    if (tid < 128) {
        int n = CB + tid;
        float bias = 0.f, w0 = 0.f, w1 = 0.f; int dep = 0;
        if (n < M_DIM)      { bias = bd[n]; w0 = Wc[2*n]; w1 = Wc[2*n+1]; dep = 1; }
        else if (n < NC)    { bias = bh[n - M_DIM]; w0 = Wc[2*n]; w1 = Wc[2*n+1]; }
        sbias[tid] = bias; sw0[tid] = w0; sw1[tid] = w1; sdep[tid] = dep;
    }

    const __nv_bfloat16* Ag = g_Xi + (size_t)R * 2048;
    const __nv_bfloat16* Bg = g_Bi + (size_t)CB * 2048;

    // ldmatrix lane address components
    const int laneA_r = (lid & 7) | (((lid >> 3) & 1) << 3);   // row within 16
    const int laneA_k = (lid >> 4) << 3;                       // 0 or 8
    const int laneB_n = (lid & 7) | ((lid >> 4) << 3);         // n within 16
    const int laneB_k = ((lid >> 3) & 1) << 3;                 // 0 or 8

    const int wm = wid & 3;           // m group: rows wm*32 .. +31
    const int wn = wid >> 2;          // n group: cols wn*64 .. +63
    const int mBase = wm * 32;
    const int nBase = wn * 64;

    float acc[2][8][4];
    #pragma unroll
    for (int i = 0; i < 2; ++i)
        #pragma unroll
        for (int j = 0; j < 8; ++j)
            #pragma unroll
            for (int e = 0; e < 4; ++e) acc[i][j][e] = 0.f;

    // cp.async mapping (per thread)
    const int ld_r   = tid >> 3;                 // base row (0..31), +32 per i
    const int ld_c16 = (tid & 7) * 16;           // byte col
    const uint32_t ld_dofs[4] = {
        SWZ128((ld_r +  0) * 128 + ld_c16),
        SWZ128((ld_r + 32) * 128 + ld_c16),
        SWZ128((ld_r + 64) * 128 + ld_c16),
        SWZ128((ld_r + 96) * 128 + ld_c16)
    };

    // issue chunk 0 into buffer 0
    #pragma unroll
    for (int i = 0; i < 4; ++i) {
        size_t ro = (size_t)(ld_r + i * 32) * 4096 + ld_c16;
        CP_ASYNC16(sbase + SM_A0 + ld_dofs[i], (const char*)Ag + ro);
        CP_ASYNC16(sbase + SM_B0 + ld_dofs[i], (const char*)Bg + ro);
    }
    CP_COMMIT();

    // cross-term k-step tables: (A kcol, B kcol) in bf16 units
    const int AKC[6] = {0, 16, 0, 16, 32, 48};
    const int BKC[6] = {0, 16, 32, 48, 0, 16};

    for (int it = 0; it < NCHUNK; ++it) {
        // prefetch next chunk into other buffer FIRST, then wait (R5 ordering).
        if (it + 1 < NCHUNK) {
            const uint32_t aOff = ((it + 1) & 1) ? SM_A1 : SM_A0;
            const uint32_t bOff = ((it + 1) & 1) ? SM_B1 : SM_B0;
            const char* An = (const char*)(Ag + (it + 1) * 64);
            const char* Bn = (const char*)(Bg + (it + 1) * 64);
            #pragma unroll
            for (int i = 0; i < 4; ++i) {
                size_t ro = (size_t)(ld_r + i * 32) * 4096 + ld_c16;
                CP_ASYNC16(sbase + aOff + ld_dofs[i], An + ro);
                CP_ASYNC16(sbase + bOff + ld_dofs[i], Bn + ro);
            }
            CP_COMMIT();
            CP_WAIT1();
        } else {
            CP_WAIT0();
        }
        __syncthreads();

        const uint32_t pA = sbase + ((it & 1) ? SM_A1 : SM_A0);
        const uint32_t pB = sbase + ((it & 1) ? SM_B1 : SM_B0);

        #pragma unroll
        for (int s = 0; s < 6; ++s) {
            const int akc = AKC[s], bkc = BKC[s];
            // issue ALL fragment loads for this k-step back-to-back so their
            // latencies overlap and ptxas can hoist next-step loads under MMAs
            uint32_t a[2][4], b[4][4];
            #pragma unroll
            for (int mi = 0; mi < 2; ++mi) {
                uint32_t addr = pA + SWZ128((mBase + mi * 16 + laneA_r) * 128 +
                                            (akc + laneA_k) * 2);
                LDSM_X4(a[mi][0], a[mi][1], a[mi][2], a[mi][3], addr);
            }
            #pragma unroll
            for (int nfp = 0; nfp < 4; ++nfp) {
                uint32_t addr = pB + SWZ128((nBase + nfp * 16 + laneB_n) * 128 +
                                            (bkc + laneB_k) * 2);
                LDSM_X4(b[nfp][0], b[nfp][1], b[nfp][2], b[nfp][3], addr);
            }
            #pragma unroll
            for (int nfp = 0; nfp < 4; ++nfp) {
                MMA16816(acc[0][2 * nfp],     a[0][0], a[0][1], a[0][2], a[0][3], b[nfp][0], b[nfp][1]);
                MMA16816(acc[1][2 * nfp],     a[1][0], a[1][1], a[1][2], a[1][3], b[nfp][0], b[nfp][1]);
                MMA16816(acc[0][2 * nfp + 1], a[0][0], a[0][1], a[0][2], a[0][3], b[nfp][2], b[nfp][3]);
                MMA16816(acc[1][2 * nfp + 1], a[1][0], a[1][1], a[1][2], a[1][3], b[nfp][2], b[nfp][3]);
            }
        }
        __syncthreads();
    }

    // ---- epilogue: bias + leaky + Wc reduce -> per-tile partial scores ----
    float pd0[4], pd1[4], ph0[4], ph1[4];
    #pragma unroll
    for (int i = 0; i < 4; ++i) { pd0[i] = pd1[i] = ph0[i] = ph1[i] = 0.f; }

    #pragma unroll
    for (int mi = 0; mi < 2; ++mi)
        #pragma unroll
        for (int nf = 0; nf < 8; ++nf)
            #pragma unroll
            for (int e = 0; e < 4; ++e) {
                int nl = nBase + nf * 8 + (lid & 3) * 2 + (e & 1);
                float v = acc[mi][nf][e] + sbias[nl];
                v = v > 0.f ? v : NEG * v;
                float w0 = sw0[nl], w1 = sw1[nl];
                int ri = mi * 2 + (e >> 1);
                if (sdep[nl]) { pd0[ri] += v * w0; pd1[ri] += v * w1; }
                else          { ph0[ri] += v * w0; ph1[ri] += v * w1; }
            }

    #pragma unroll
    for (int off = 2; off >= 1; off >>= 1)
        #pragma unroll
        for (int i = 0; i < 4; ++i) {
            pd0[i] += __shfl_xor_sync(0xffffffffu, pd0[i], off);
            pd1[i] += __shfl_xor_sync(0xffffffffu, pd1[i], off);
            ph0[i] += __shfl_xor_sync(0xffffffffu, ph0[i], off);
            ph1[i] += __shfl_xor_sync(0xffffffffu, ph1[i], off);
        }

    // combine wn=0 and wn=1 halves via smem stage (reuse A0 buffer)
    float* stage = reinterpret_cast<float*>(dsm);
    __syncthreads();   // all compute reads done -> safe to reuse smem

    if ((lid & 3) == 0 && wn == 0) {
        #pragma unroll
        for (int i = 0; i < 4; ++i) {
            int rl = mBase + (i >> 1) * 16 + (lid >> 2) + (i & 1) * 8;
            stage[rl * 4 + 0] = pd0[i];
            stage[rl * 4 + 1] = pd1[i];
            stage[rl * 4 + 2] = ph0[i];
            stage[rl * 4 + 3] = ph1[i];
        }
    }
    __syncthreads();
    if ((lid & 3) == 0 && wn == 1) {
        const int tile = blockIdx.x;
        #pragma unroll
        for (int i = 0; i < 4; ++i) {
            int rl = mBase + (i >> 1) * 16 + (lid >> 2) + (i & 1) * 8;
            int row = R + rl;
            g_partD[tile][row][0] = pd0[i] + stage[rl * 4 + 0];
            g_partD[tile][row][1] = pd1[i] + stage[rl * 4 + 1];
            g_partH[tile][row][0] = ph0[i] + stage[rl * 4 + 2];
            g_partH[tile][row][1] = ph1[i] + stage[rl * 4 + 3];
        }
    }
}

// sum the 8 column-tile partials -> g_scores
__global__ __launch_bounds__(256)
void reduce_scores()
{
    int row = blockIdx.x * blockDim.x + threadIdx.x;
    float d0 = 0.f, d1 = 0.f, h0 = 0.f, h1 = 0.f;
    #pragma unroll
    for (int t = 0; t < 8; ++t) {
        d0 += g_partD[t][row][0];
        d1 += g_partD[t][row][1];
        h0 += g_partH[t][row][0];
        h1 += g_partH[t][row][1];
    }
    g_scores[row * 2 + 0] = d0;
    g_scores[row * 2 + 1] = d1;
    g_scores[2 * BL_MAX + row * 2 + 0] = h0;
    g_scores[2 * BL_MAX + row * 2 + 1] = h1;
}

// out[b, i, j, c] = dep[b,i,c] + head[b,j,c] + bc[c]
__global__ __launch_bounds__(256)
void bcast_kernel(const float* __restrict__ bc, float* __restrict__ out)
{
    const float* ds = g_scores;
    const float* hs = g_scores + 2 * BL_MAX;
    const int n = blockIdx.x;                  // b*1024 + i
    const int b = n >> 10;
    const float base0 = ds[n * 2 + 0] + bc[0];
    const float base1 = ds[n * 2 + 1] + bc[1];
    const float4* hv = reinterpret_cast<const float4*>(hs + (size_t)b * 2048);
    float4* o = reinterpret_cast<float4*>(out + (size_t)n * 2048);
    #pragma unroll
    for (int t = threadIdx.x; t < 512; t += 256) {
        float4 h = hv[t];
        o[t] = make_float4(base0 + h.x, base1 + h.y, base0 + h.z, base1 + h.w);
    }
}

extern "C" void kernel_launch(void* const* d_in, const int* in_sizes, int n_in,
                              void* d_out, int out_size)
{
    const float* X  = (const float*)d_in[0];
    const float* Wd = (const float*)d_in[1];
    const float* bd = (const float*)d_in[2];
    const float* Wh = (const float*)d_in[3];
    const float* bh = (const float*)d_in[4];
    const float* Wc = (const float*)d_in[5];
    const float* bc = (const float*)d_in[6];
    float* out = (float*)d_out;

    const int BL = in_sizes[0] / D_DIM;        // 16384

    static int smem_set = 0;
    if (!smem_set) {
        cudaFuncSetAttribute(gemm_mma, cudaFuncAttributeMaxDynamicSharedMemorySize, SM_TOTAL);
        smem_set = 1;
    }

    // harness issues ~2 internal launches first; ncu -s 5 -c 1 captures MY index 3 = gemm_mma
    convW<<<dim3(32, 16), dim3(32, 8)>>>(Wd, Wh, 0);                 // 0
    convW<<<dim3(32, 16), dim3(32, 8)>>>(Wd, Wh, 16);                // 1
    convX<<<(BL * D_DIM / 4 + 255) / 256, 256>>>(X);                 // 2
    gemm_mma<<<dim3(NPAD / NT, BL / MT), GTHREADS, SM_TOTAL>>>(bd, bh, Wc);  // 3
    reduce_scores<<<BL / 256, 256>>>();                              // 4
    bcast_kernel<<<BL, 256>>>(bc, out);                              // 5
}

// round 14
// speedup vs baseline: 1.1610x; 1.0147x over previous
#include <cuda_runtime.h>
#include <cuda_bf16.h>
#include <cstdint>

// BinaryBiaffine2 via warp-level bf16 mma.sync: scores = leaky(X@W+b)@Wc, broadcast add.
// fp32 -> 2-way bf16 split (hi+lo), 3 cross-term GEMMs fused as K-steps.
// R10-R14: MT=64 / warp tile 32x32 -> acc 32 regs, occ 3, grid 2048 (finer waves).

#define D_DIM 1024
#define M_DIM 500
#define NC    1000
#define NPAD  1024
#define BL_MAX 16384
#define NEG   0.01f

#define MT 64
#define NT 128
#define NCHUNK 32
#define GTHREADS 256

// dynamic smem: 2 stages x (A 8KB + B 16KB) + tables
#define SM_A0 0
#define SM_B0 8192
#define SM_A1 24576
#define SM_B1 32768
#define SM_TAB 49152
#define SM_TOTAL (49152 + 2048)

// ---- scratch (static device globals; allocation-guard-safe) ----
__device__ __nv_bfloat16 g_Xi[(size_t)BL_MAX * 2048];   // [row][chunk*64 + half*32 + j]
__device__ __nv_bfloat16 g_Bi[(size_t)NPAD * 2048];     // [n][chunk*64 + half*32 + j]
__device__ float g_partD[8][BL_MAX][2];                 // per-column-tile dep partials
__device__ float g_partH[8][BL_MAX][2];                 // per-column-tile head partials
__device__ float g_scores[BL_MAX * 4];                  // final: dep [0,2BL), head [2BL,4BL)

// ============================ PTX helpers ============================
__device__ __forceinline__ uint32_t smem_u32(const void* p) {
    uint32_t a;
    asm("{ .reg .u64 t; cvta.to.shared.u64 t, %1; cvt.u32.u64 %0, t; }" : "=r"(a) : "l"(p));
    return a;
}
#define SWZ128(x) ((x) ^ (((x) >> 3) & 0x70))

#define CP_ASYNC16(dst, src) \
    asm volatile("cp.async.cg.shared.global [%0], [%1], 16;" :: "r"(dst), "l"(src))
#define CP_COMMIT() asm volatile("cp.async.commit_group;" ::: "memory")
#define CP_WAIT1()  asm volatile("cp.async.wait_group 1;" ::: "memory")
#define CP_WAIT0()  asm volatile("cp.async.wait_group 0;" ::: "memory")

#define LDSM_X4(r0, r1, r2, r3, addr) \
    asm volatile("ldmatrix.sync.aligned.m8n8.x4.shared.b16 {%0,%1,%2,%3}, [%4];" \
                 : "=r"(r0), "=r"(r1), "=r"(r2), "=r"(r3) : "r"(addr))

#define MMA16816(d, a0, a1, a2, a3, b0, b1) \
    asm volatile("mma.sync.aligned.m16n8k16.row.col.f32.bf16.bf16.f32 " \
                 "{%0,%1,%2,%3}, {%4,%5,%6,%7}, {%8,%9}, {%0,%1,%2,%3};" \
                 : "+f"((d)[0]), "+f"((d)[1]), "+f"((d)[2]), "+f"((d)[3]) \
                 : "r"(a0), "r"(a1), "r"(a2), "r"(a3), "r"(b0), "r"(b1))

// ============================ converters ============================
__global__ void convX(const float* __restrict__ X) {
    size_t i = (size_t)blockIdx.x * blockDim.x + threadIdx.x;   // one float4 each
    const float4 v = reinterpret_cast<const float4*>(X)[i];
    size_t row = i >> 8;              // 256 float4 per 1024-col row
    int col = (int)(i & 255) * 4;
    int chunk = col >> 5, j = col & 31;
    __nv_bfloat16* o = g_Xi + row * 2048 + (size_t)chunk * 64 + j;

    __nv_bfloat16 h0 = __float2bfloat16(v.x), h1 = __float2bfloat16(v.y);
    __nv_bfloat16 h2 = __float2bfloat16(v.z), h3 = __float2bfloat16(v.w);
    __nv_bfloat16 l0 = __float2bfloat16(v.x - __bfloat162float(h0));
    __nv_bfloat16 l1 = __float2bfloat16(v.y - __bfloat162float(h1));
    __nv_bfloat16 l2 = __float2bfloat16(v.z - __bfloat162float(h2));
    __nv_bfloat16 l3 = __float2bfloat16(v.w - __bfloat162float(h3));

    __nv_bfloat162* oh = reinterpret_cast<__nv_bfloat162*>(o);
    __nv_bfloat162* ol = reinterpret_cast<__nv_bfloat162*>(o + 32);
    oh[0] = __nv_bfloat162(h0, h1); oh[1] = __nv_bfloat162(h2, h3);
    ol[0] = __nv_bfloat162(l0, l1); ol[1] = __nv_bfloat162(l2, l3);
}

// Transpose W_dep|W_head (fp32 [d][m]) into g_Bi [n][2048] bf16 hi|lo interleaved.
__global__ void convW(const float* __restrict__ Wd, const float* __restrict__ Wh, int y0) {
    __shared__ float t[32][33];
    const int m0 = blockIdx.x * 32, d0 = (blockIdx.y + y0) * 32;
    const int tx = threadIdx.x, ty = threadIdx.y;     // 32 x 8
    #pragma unroll
    for (int yy = ty; yy < 32; yy += 8) {
        int m = m0 + tx, d = d0 + yy;
        float v = 0.0f;
        if (m < M_DIM)      v = Wd[(size_t)d * M_DIM + m];
        else if (m < NC)    v = Wh[(size_t)d * M_DIM + (m - M_DIM)];
        t[yy][tx] = v;
    }
    __syncthreads();
    #pragma unroll
    for (int yy = ty; yy < 32; yy += 8) {
        int n = m0 + yy;
        float v = t[tx][yy];
        __nv_bfloat16 h = __float2bfloat16(v);
        __nv_bfloat16 l = __float2bfloat16(v - __bfloat162float(h));
        size_t ob = (size_t)n * 2048 + (size_t)(d0 >> 5) * 64 + tx;
        g_Bi[ob] = h;
        g_Bi[ob + 32] = l;
    }
}

// ============================ HMMA GEMM + fused epilogue ============================
__global__ __launch_bounds__(GTHREADS, 3)
void gemm_mma(const float* __restrict__ bd, const float* __restrict__ bh,
              const float* __restrict__ Wc)
{
    extern __shared__ char dsm[];
    const uint32_t sbase = smem_u32(dsm);

    const int tid = threadIdx.x;
    const int wid = tid >> 5, lid = tid & 31;
    const int CB  = blockIdx.x * NT;      // n base
    const int R   = blockIdx.y * MT;      // m base

    float* sbias = reinterpret_cast<float*>(dsm + SM_TAB);
    float* sw0   = sbias + 128;
    float* sw1   = sbias + 256;
    int*   sdep  = reinterpret_cast<int*>(sbias + 384);

    if (tid < 128) {
        int n = CB + tid;
        float bias = 0.f, w0 = 0.f, w1 = 0.f; int dep = 0;
        if (n < M_DIM)      { bias = bd[n]; w0 = Wc[2*n]; w1 = Wc[2*n+1]; dep = 1; }
        else if (n < NC)    { bias = bh[n - M_DIM]; w0 = Wc[2*n]; w1 = Wc[2*n+1]; }
        sbias[tid] = bias; sw0[tid] = w0; sw1[tid] = w1; sdep[tid] = dep;
    }

    const __nv_bfloat16* Ag = g_Xi + (size_t)R * 2048;
    const __nv_bfloat16* Bg = g_Bi + (size_t)CB * 2048;

    // ldmatrix lane address components
    const int laneA_r = (lid & 7) | (((lid >> 3) & 1) << 3);   // row within 16
    const int laneA_k = (lid >> 4) << 3;                       // 0 or 8
    const int laneB_n = (lid & 7) | ((lid >> 4) << 3);         // n within 16
    const int laneB_k = ((lid >> 3) & 1) << 3;                 // 0 or 8

    const int wm = wid & 1;           // m group: rows wm*32 .. +31
    const int wn = wid >> 1;          // n group: cols wn*32 .. +31
    const int mBase = wm * 32;
    const int nBase = wn * 32;

    float acc[2][4][4];               // [mi][nf][e], warp tile 32x32
    #pragma unroll
    for (int i = 0; i < 2; ++i)
        #pragma unroll
        for (int j = 0; j < 4; ++j)
            #pragma unroll
            for (int e = 0; e < 4; ++e) acc[i][j][e] = 0.f;

    // cp.async mapping (per thread)
    const int ld_r   = tid >> 3;                 // base row (0..31), +32 per i
    const int ld_c16 = (tid & 7) * 16;           // byte col
    const uint32_t ld_dofs[4] = {
        SWZ128((ld_r +  0) * 128 + ld_c16),
        SWZ128((ld_r + 32) * 128 + ld_c16),
        SWZ128((ld_r + 64) * 128 + ld_c16),
        SWZ128((ld_r + 96) * 128 + ld_c16)
    };

    // issue chunk 0 into buffer 0 (A: 64 rows = 2 passes; B: 128 rows = 4 passes)
    #pragma unroll
    for (int i = 0; i < 2; ++i) {
        size_t ro = (size_t)(ld_r + i * 32) * 4096 + ld_c16;
        CP_ASYNC16(sbase + SM_A0 + ld_dofs[i], (const char*)Ag + ro);
    }
    #pragma unroll
    for (int i = 0; i < 4; ++i) {
        size_t ro = (size_t)(ld_r + i * 32) * 4096 + ld_c16;
        CP_ASYNC16(sbase + SM_B0 + ld_dofs[i], (const char*)Bg + ro);
    }
    CP_COMMIT();

    // cross-term k-step tables: (A kcol, B kcol) in bf16 units
    const int AKC[6] = {0, 16, 0, 16, 32, 48};
    const int BKC[6] = {0, 16, 32, 48, 0, 16};

    for (int it = 0; it < NCHUNK; ++it) {
        // prefetch next chunk into other buffer FIRST, then wait (R5 ordering).
        if (it + 1 < NCHUNK) {
            const uint32_t aOff = ((it + 1) & 1) ? SM_A1 : SM_A0;
            const uint32_t bOff = ((it + 1) & 1) ? SM_B1 : SM_B0;
            const char* An = (const char*)(Ag + (it + 1) * 64);
            const char* Bn = (const char*)(Bg + (it + 1) * 64);
            #pragma unroll
            for (int i = 0; i < 2; ++i) {
                size_t ro = (size_t)(ld_r + i * 32) * 4096 + ld_c16;
                CP_ASYNC16(sbase + aOff + ld_dofs[i], An + ro);
            }
            #pragma unroll
            for (int i = 0; i < 4; ++i) {
                size_t ro = (size_t)(ld_r + i * 32) * 4096 + ld_c16;
                CP_ASYNC16(sbase + bOff + ld_dofs[i], Bn + ro);
            }
            CP_COMMIT();
            CP_WAIT1();
        } else {
            CP_WAIT0();
        }
        __syncthreads();

        const uint32_t pA = sbase + ((it & 1) ? SM_A1 : SM_A0);
        const uint32_t pB = sbase + ((it & 1) ? SM_B1 : SM_B0);

        #pragma unroll
        for (int s = 0; s < 6; ++s) {
            const int akc = AKC[s], bkc = BKC[s];
            uint32_t a[2][4], b[2][4];
            #pragma unroll
            for (int mi = 0; mi < 2; ++mi) {
                uint32_t addr = pA + SWZ128((mBase + mi * 16 + laneA_r) * 128 +
                                            (akc + laneA_k) * 2);
                LDSM_X4(a[mi][0], a[mi][1], a[mi][2], a[mi][3], addr);
            }
            #pragma unroll
            for (int nfp = 0; nfp < 2; ++nfp) {
                uint32_t addr = pB + SWZ128((nBase + nfp * 16 + laneB_n) * 128 +
                                            (bkc + laneB_k) * 2);
                LDSM_X4(b[nfp][0], b[nfp][1], b[nfp][2], b[nfp][3], addr);
            }
            #pragma unroll
            for (int nfp = 0; nfp < 2; ++nfp) {
                MMA16816(acc[0][2 * nfp],     a[0][0], a[0][1], a[0][2], a[0][3], b[nfp][0], b[nfp][1]);
                MMA16816(acc[1][2 * nfp],     a[1][0], a[1][1], a[1][2], a[1][3], b[nfp][0], b[nfp][1]);
                MMA16816(acc[0][2 * nfp + 1], a[0][0], a[0][1], a[0][2], a[0][3], b[nfp][2], b[nfp][3]);
                MMA16816(acc[1][2 * nfp + 1], a[1][0], a[1][1], a[1][2], a[1][3], b[nfp][2], b[nfp][3]);
            }
        }
        __syncthreads();
    }

    // ---- epilogue: bias + leaky + Wc reduce -> per-tile partial scores ----
    // acc (mi, nf, e): row = mBase + mi*16 + (lid>>2) + (e>>1)*8
    //                  n_local = nBase + nf*8 + (lid&3)*2 + (e&1)
    float pd0[4], pd1[4], ph0[4], ph1[4];
    #pragma unroll
    for (int i = 0; i < 4; ++i) { pd0[i] = pd1[i] = ph0[i] = ph1[i] = 0.f; }

    #pragma unroll
    for (int mi = 0; mi < 2; ++mi)
        #pragma unroll
        for (int nf = 0; nf < 4; ++nf)
            #pragma unroll
            for (int e = 0; e < 4; ++e) {
                int nl = nBase + nf * 8 + (lid & 3) * 2 + (e & 1);
                float v = acc[mi][nf][e] + sbias[nl];
                v = v > 0.f ? v : NEG * v;
                float w0 = sw0[nl], w1 = sw1[nl];
                int ri = mi * 2 + (e >> 1);
                if (sdep[nl]) { pd0[ri] += v * w0; pd1[ri] += v * w1; }
                else          { ph0[ri] += v * w0; ph1[ri] += v * w1; }
            }

    #pragma unroll
    for (int off = 2; off >= 1; off >>= 1)
        #pragma unroll
        for (int i = 0; i < 4; ++i) {
            pd0[i] += __shfl_xor_sync(0xffffffffu, pd0[i], off);
            pd1[i] += __shfl_xor_sync(0xffffffffu, pd1[i], off);
            ph0[i] += __shfl_xor_sync(0xffffffffu, ph0[i], off);
            ph1[i] += __shfl_xor_sync(0xffffffffu, ph1[i], off);
        }

    // combine the 4 wn groups per row via smem stage (reuse A0 region: need 3KB)
    float* stage = reinterpret_cast<float*>(dsm);   // stage[wn][rl][4], wn<3
    __syncthreads();   // all compute reads done -> safe to reuse smem

    if ((lid & 3) == 0 && wn < 3) {
        #pragma unroll
        for (int i = 0; i < 4; ++i) {
            int rl = mBase + (i >> 1) * 16 + (lid >> 2) + (i & 1) * 8;
            int sb = (wn * 64 + rl) * 4;
            stage[sb + 0] = pd0[i];
            stage[sb + 1] = pd1[i];
            stage[sb + 2] = ph0[i];
            stage[sb + 3] = ph1[i];
        }
    }
    __syncthreads();
    if ((lid & 3) == 0 && wn == 3) {
        const int tile = blockIdx.x;
        #pragma unroll
        for (int i = 0; i < 4; ++i) {
            int rl = mBase + (i >> 1) * 16 + (lid >> 2) + (i & 1) * 8;
            int row = R + rl;
            float d0 = pd0[i], d1 = pd1[i], h0 = ph0[i], h1 = ph1[i];
            #pragma unroll
            for (int w = 0; w < 3; ++w) {
                int sb = (w * 64 + rl) * 4;
                d0 += stage[sb + 0];
                d1 += stage[sb + 1];
                h0 += stage[sb + 2];
                h1 += stage[sb + 3];
            }
            g_partD[tile][row][0] = d0;
            g_partD[tile][row][1] = d1;
            g_partH[tile][row][0] = h0;
            g_partH[tile][row][1] = h1;
        }
    }
}

// sum the 8 column-tile partials -> g_scores
__global__ __launch_bounds__(256)
void reduce_scores()
{
    int row = blockIdx.x * blockDim.x + threadIdx.x;
    float d0 = 0.f, d1 = 0.f, h0 = 0.f, h1 = 0.f;
    #pragma unroll
    for (int t = 0; t < 8; ++t) {
        d0 += g_partD[t][row][0];
        d1 += g_partD[t][row][1];
        h0 += g_partH[t][row][0];
        h1 += g_partH[t][row][1];
    }
    g_scores[row * 2 + 0] = d0;
    g_scores[row * 2 + 1] = d1;
    g_scores[2 * BL_MAX + row * 2 + 0] = h0;
    g_scores[2 * BL_MAX + row * 2 + 1] = h1;
}

// out[b, i, j, c] = dep[b,i,c] + head[b,j,c] + bc[c]
__global__ __launch_bounds__(256)
void bcast_kernel(const float* __restrict__ bc, float* __restrict__ out)
{
    const float* ds = g_scores;
    const float* hs = g_scores + 2 * BL_MAX;
    const int n = blockIdx.x;                  // b*1024 + i
    const int b = n >> 10;
    const float base0 = ds[n * 2 + 0] + bc[0];
    const float base1 = ds[n * 2 + 1] + bc[1];
    const float4* hv = reinterpret_cast<const float4*>(hs + (size_t)b * 2048);
    float4* o = reinterpret_cast<float4*>(out + (size_t)n * 2048);
    #pragma unroll
    for (int t = threadIdx.x; t < 512; t += 256) {
        float4 h = hv[t];
        o[t] = make_float4(base0 + h.x, base1 + h.y, base0 + h.z, base1 + h.w);
    }
}

extern "C" void kernel_launch(void* const* d_in, const int* in_sizes, int n_in,
                              void* d_out, int out_size)
{
    const float* X  = (const float*)d_in[0];
    const float* Wd = (const float*)d_in[1];
    const float* bd = (const float*)d_in[2];
    const float* Wh = (const float*)d_in[3];
    const float* bh = (const float*)d_in[4];
    const float* Wc = (const float*)d_in[5];
    const float* bc = (const float*)d_in[6];
    float* out = (float*)d_out;

    const int BL = in_sizes[0] / D_DIM;        // 16384

    static int smem_set = 0;
    if (!smem_set) {
        cudaFuncSetAttribute(gemm_mma, cudaFuncAttributeMaxDynamicSharedMemorySize, SM_TOTAL);
        smem_set = 1;
    }

    // harness issues ~2 internal launches first; ncu -s 5 -c 1 captures MY index 3 = gemm_mma
    convW<<<dim3(32, 16), dim3(32, 8)>>>(Wd, Wh, 0);                 // 0
    convW<<<dim3(32, 16), dim3(32, 8)>>>(Wd, Wh, 16);                // 1
    convX<<<(BL * D_DIM / 4 + 255) / 256, 256>>>(X);                 // 2
    gemm_mma<<<dim3(NPAD / NT, BL / MT), GTHREADS, SM_TOTAL>>>(bd, bh, Wc);  // 3
    reduce_scores<<<BL / 256, 256>>>();                              // 4
    bcast_kernel<<<BL, 256>>>(bc, out);                              // 5
}